// round 12
// baseline (speedup 1.0000x reference)
#include <cuda_runtime.h>

#define TT 300
#define NB 4

// f32-rounded versions of the reference's double constants
#define DCAY 0.8187307530779818f   // exp(-1/5)
#define PSPS 0.5436563656918091f   // e/5
#define REFS 1.3591409142295226f   // 2*1.25*e/5
#define THR  1.25f
#define PW   1.375f                // 1.1*theta (exact in f32)

#define KC 248                     // Eigen depth-panel size (ARM defaults)

typedef unsigned long long u64;

// ---- packed f32x2 helpers: per-lane rounding identical to scalar FFMA/FADD ----
__device__ __forceinline__ u64 pk2(float v){
    u64 r; asm("mov.b64 %0, {%1, %1};" : "=l"(r) : "f"(v)); return r;
}
__device__ __forceinline__ u64 fma2(u64 v, u64 w, u64 a){
    u64 r; asm("fma.rn.f32x2 %0, %1, %2, %3;" : "=l"(r) : "l"(v), "l"(w), "l"(a)); return r;
}
__device__ __forceinline__ u64 add2(u64 a, u64 b){
    u64 r; asm("add.rn.f32x2 %0, %1, %2;" : "=l"(r) : "l"(a), "l"(b)); return r;
}

// ---- scratch, time-major, CHANNEL-MINOR spatial layouts ----
__device__ float g_buf0[TT*8192];     // [t][4][32][32][2]   pool0 raw -> spikes (in place)
__device__ float g_buf1[TT*131072];   // [t][4][32][32][32]  conv1 raw
__device__ float g_buf2[TT*32768];    // [t][4][16][16][32]  layer-2 input spikes
__device__ float g_buf3[TT*65536];    // [t][4][16][16][64]  conv2 raw
__device__ float g_buf4[TT*16384];    // [t][4][8][8][64]    layer-3 input spikes
__device__ float g_buf5[TT*32768];    // [t][4][8][8][128]   conv3 raw
__device__ float g_buf6[TT*8192];     // [t][4][4][4][128]   dense input spikes
__device__ float g_buf7[TT*1024];     // [t][4][256]
__device__ float g_buf8[TT*44];       // [t][4][11]

// weights transposed to [kh][kw][ci][oc] (HWIO): k-ascending == (kh,kw,ci), ci fastest
__device__ __align__(16) float g_w1t[50*32];
__device__ __align__(16) float g_w2t[288*64];
__device__ __align__(16) float g_w3t[576*128];
__device__ __align__(16) float g_w4at[2048*256];   // [k][o], k = reference (c,h,w) flatten

// ---------------- merged weight transpose (single launch) ----------------
__global__ void prep_all_k(const float* __restrict__ w1, const float* __restrict__ w2,
                           const float* __restrict__ w3, const float* __restrict__ w4a){
    int i = blockIdx.x*256 + threadIdx.x;
    if (i < 32*50){
        int o = i/50, rem = i%50;
        int c = rem/25, r = rem%25, kh = r/5, kw = r%5;
        g_w1t[((kh*5+kw)*2 + c)*32 + o] = w1[i];
    }
    if (i < 64*288){
        int o = i/288, rem = i%288;
        int ci = rem/9, r = rem%9, kh = r/3, kw = r%3;
        g_w2t[((kh*3+kw)*32 + ci)*64 + o] = w2[i];
    }
    if (i < 128*576){
        int o = i/576, rem = i%576;
        int ci = rem/9, r = rem%9, kh = r/3, kw = r%3;
        g_w3t[((kh*3+kw)*64 + ci)*128 + o] = w3[i];
    }
    if (i < 256*2048){
        int o = i/2048, k = i%2048;
        g_w4at[k*256+o] = w4a[i];
    }
}

// ---------------- stage 0: 4x4 sum-pool (binary inputs -> exact) ----------------
__global__ void pool0_kernel(const float* __restrict__ s){
    int t = blockIdx.x*32 + threadIdx.x;
    int n = blockIdx.y*blockDim.y + threadIdx.y;   // b*2048+(oh*32+ow)*2+c
    if (t >= TT) return;
    int c = n & 1, ow = (n>>1)&31, oh = (n>>6)&31, b = n>>11;
    const float* base = s + (size_t)(((b*2+c)*128 + oh*4)*128 + ow*4)*TT + t;
    float acc = 0.f;
    #pragma unroll
    for (int i=0;i<4;i++)
        #pragma unroll
        for (int j=0;j<4;j++)
            acc += base[(i*128+j)*TT];
    g_buf0[(size_t)t*8192 + n] = acc * PW;
}

// ---------------- fused PSP + refractory + threshold scan (strict rn) ----------
__global__ void scan_kernel(float* __restrict__ buf, int N){
    int n = blockIdx.x*blockDim.x + threadIdx.x;
    if (n >= N) return;
    float s1=0.f, s2=0.f, r1=0.f, r2=0.f;
    size_t idx = n;
    #pragma unroll 4
    for (int t=0; t<TT; t++, idx += N){
        float x = buf[idx];
        s2 = __fmul_rn(DCAY, __fadd_rn(s2, s1));
        s1 = __fadd_rn(__fmul_rn(DCAY, s1), x);
        r2 = __fmul_rn(DCAY, __fadd_rn(r2, r1));
        r1 = __fmul_rn(DCAY, r1);
        float u = __fmul_rn(PSPS, s2);
        float v = __fsub_rn(__fsub_rn(u, __fmul_rn(REFS, r2)), THR);
        float spk = (v >= 0.f) ? 1.f : 0.f;
        r1 = __fadd_rn(r1, spk);
        buf[idx] = spk;
    }
}

// ---------------- fused: scan(conv raw) -> 2x2 pool -> scan(pooled) ------------
// Bit-identical to the scan + pool + scan chain: same strict-rn op sequence per
// t-step; pool sums of 4 binary spikes are exact.
template<int C, int Hin>
__global__ void scan2_pool_kernel(const float* __restrict__ in, float* __restrict__ out){
    const int Ho = Hin/2;
    const int Npool = 4*C*Ho*Ho;
    const int Tin = 4*C*Hin*Hin;
    int n = blockIdx.x*256 + threadIdx.x;   // grid sized exactly
    int c = n & (C-1);
    int r = n / C;
    int ow = r % Ho; r /= Ho;
    int oh = r % Ho;
    int b = r / Ho;
    size_t base = ((size_t)(b*Hin + 2*oh)*Hin + 2*ow)*C + c;
    float S1[4]={0,0,0,0}, S2[4]={0,0,0,0}, R1[4]={0,0,0,0}, R2[4]={0,0,0,0};
    float ps1=0.f, ps2=0.f, pr1=0.f, pr2=0.f;
    const int off1 = C, off2 = Hin*C, off3 = Hin*C + C;
    #pragma unroll 2
    for (int t=0; t<TT; t++){
        const float* p = in + (size_t)t*Tin + base;
        float x0 = p[0], x1 = p[off1], x2 = p[off2], x3 = p[off3];
        float xs[4] = {x0, x1, x2, x3};
        float sum = 0.f;
        #pragma unroll
        for (int j=0;j<4;j++){
            S2[j] = __fmul_rn(DCAY, __fadd_rn(S2[j], S1[j]));
            S1[j] = __fadd_rn(__fmul_rn(DCAY, S1[j]), xs[j]);
            R2[j] = __fmul_rn(DCAY, __fadd_rn(R2[j], R1[j]));
            R1[j] = __fmul_rn(DCAY, R1[j]);
            float u = __fmul_rn(PSPS, S2[j]);
            float v = __fsub_rn(__fsub_rn(u, __fmul_rn(REFS, R2[j])), THR);
            float spk = (v >= 0.f) ? 1.f : 0.f;
            R1[j] = __fadd_rn(R1[j], spk);
            sum += spk;                         // exact: small integers
        }
        float x = sum * PW;                     // exact: sum<=4, *1.375
        ps2 = __fmul_rn(DCAY, __fadd_rn(ps2, ps1));
        ps1 = __fadd_rn(__fmul_rn(DCAY, ps1), x);
        pr2 = __fmul_rn(DCAY, __fadd_rn(pr2, pr1));
        pr1 = __fmul_rn(DCAY, pr1);
        float u = __fmul_rn(PSPS, ps2);
        float v = __fsub_rn(__fsub_rn(u, __fmul_rn(REFS, pr2)), THR);
        float spk = (v >= 0.f) ? 1.f : 0.f;
        pr1 = __fadd_rn(pr1, spk);
        out[(size_t)t*Npool + n] = spk;
    }
}

// packed fma-chain: NU u64 accumulators per thread, one ci chain segment
template<int NU>
__device__ __forceinline__ void accP(u64* acc, const float* __restrict__ trow,
                                     const u64* __restrict__ wbase, int strideU,
                                     int ci0, int ci1){
    for (int ci=ci0; ci<ci1; ci++){
        u64 vv = pk2(trow[ci]);
        const ulonglong2* w = (const ulonglong2*)(wbase + ci*strideU);
        #pragma unroll
        for (int q=0;q<NU/2;q++){
            ulonglong2 w2 = w[q];
            acc[2*q]   = fma2(vv, w2.x, acc[2*q]);
            acc[2*q+1] = fma2(vv, w2.y, acc[2*q+1]);
        }
    }
}

// ---------------- conv1: 2->32, 5x5 pad2, 32x32. K=50 < KC: single chain ------
__global__ void __launch_bounds__(512,1) conv1_kernel(){
    int tb = blockIdx.x; int b = tb & 3; int t = tb >> 2;
    __shared__ float tile[36*36*2];
    __shared__ __align__(16) float ws[50*32];
    int tid = threadIdx.y*32 + threadIdx.x;   // (32,16)=512
    const float* inp = g_buf0 + (size_t)t*8192 + b*2048;
    for (int i = tid; i < 36*36*2; i += 512){
        int c = i & 1; int xy = i >> 1; int x = xy % 36; int y = xy / 36;
        int h = y-2, w = x-2;
        float v = 0.f;
        if ((unsigned)h < 32u && (unsigned)w < 32u) v = inp[(h*32+w)*2 + c];
        tile[i] = v;
    }
    for (int i = tid; i < 400; i += 512) ((float4*)ws)[i] = ((const float4*)g_w1t)[i];
    __syncthreads();
    int ox = threadIdx.x;
    const u64* ws64 = (const u64*)ws;
    for (int s = 0; s < 2; s++){
        int oy = threadIdx.y + s*16;
        u64 acc[16];
        #pragma unroll
        for (int i=0;i<16;i++) acc[i]=0ULL;
        for (int kh=0;kh<5;kh++)
            #pragma unroll
            for (int kw=0;kw<5;kw++){
                const float* trow = tile + ((oy+kh)*36 + ox+kw)*2;
                accP<16>(acc, trow, ws64 + ((kh*5+kw)*2)*16, 16, 0, 2);
            }
        float2* op = (float2*)(g_buf1 + (size_t)t*131072 + b*32768 + (oy*32+ox)*32);
        #pragma unroll
        for (int q=0;q<16;q++) op[q] = *reinterpret_cast<float2*>(&acc[q]);
    }
}

// ---------------- conv2: 32->64, 3x3 pad1, 16x16. K=288 = 248 + 40 ------------
// k = tap*32 + ci. Panel boundary k=248 -> tap7 ci24.
// Panel B (small) computed FIRST into acc, stashed in smem; registers reused for
// panel A; combined with one add2 (fadd is bitwise-commutative -> same values).
extern __shared__ float s_dyn[];
__global__ void __launch_bounds__(512,1) conv2_kernel(){
    int tb = blockIdx.x; int b = tb & 3; int t = tb >> 2;
    float* tile = s_dyn;                    // [18][18][32]  10368 f
    float* wsm  = s_dyn + 10368;            // [9 tap][32 ci][64 oc] 18432 f
    u64*  stash = (u64*)(s_dyn + 28800);    // 512 thr x 16 u64 = 64 KB
    int tx = threadIdx.x, ty = threadIdx.y, tz = threadIdx.z;  // (16,16,2)
    int tid = (tz*16 + ty)*16 + tx;                             // 0..511
    const float* inp = g_buf2 + (size_t)t*32768 + b*8192;
    for (int i = tid; i < 10368; i += 512){
        int c = i & 31; int xy = i >> 5; int x = xy % 18; int y = xy / 18;
        int h = y-1, w = x-1;
        float v = 0.f;
        if ((unsigned)h < 16u && (unsigned)w < 16u) v = inp[(h*16+w)*32 + c];
        tile[i] = v;
    }
    for (int i = tid; i < 4608; i += 512) ((float4*)wsm)[i] = ((const float4*)g_w2t)[i];
    __syncthreads();
    int ox = tx, oy = ty, og = tz;
    const u64* wsm64 = (const u64*)wsm;
    u64 acc[16];
    #pragma unroll
    for (int i=0;i<16;i++) acc[i]=0ULL;
    const float* trow7 = tile + ((oy+2)*18 + ox+1)*32;
    const float* trow8 = tile + ((oy+2)*18 + ox+2)*32;
    // panel B: tap7 ci>=24, tap8 full  (computed first; order vs A irrelevant)
    accP<16>(acc, trow7, wsm64 + 7*1024 + og*16, 32, 24, 32);
    accP<16>(acc, trow8, wsm64 + 8*1024 + og*16, 32, 0, 32);
    u64* st = stash + tid*16;
    #pragma unroll
    for (int i=0;i<16;i++){ st[i] = acc[i]; acc[i] = 0ULL; }
    // panel A: taps 0..6 full, tap7 ci<24
    for (int tap=0; tap<7; tap++){
        const float* trow = tile + ((oy + tap/3)*18 + ox + tap%3)*32;
        accP<16>(acc, trow, wsm64 + tap*1024 + og*16, 32, 0, 32);
    }
    accP<16>(acc, trow7, wsm64 + 7*1024 + og*16, 32, 0, 24);
    // combine panels (single rounding event, same as reference's C += panel)
    #pragma unroll
    for (int i=0;i<16;i++) acc[i] = add2(acc[i], st[i]);
    float2* op = (float2*)(g_buf3 + (size_t)t*65536 + b*16384 + (oy*16+ox)*64 + og*32);
    #pragma unroll
    for (int q=0;q<16;q++) op[q] = *reinterpret_cast<float2*>(&acc[q]);
}

// ---------------- conv3: 64->128, 3x3 pad1, 8x8. K=576 = 248+248+80 -----------
// k = tap*64 + ci. Boundaries: k=248 (tap3 ci56), k=496 (tap7 ci48).
__global__ void __launch_bounds__(512,1) conv3_kernel(){
    int tb = blockIdx.x; int b = tb & 3; int t = tb >> 2;
    float* tile = s_dyn;            // [10][10][64]
    float* wsm  = s_dyn + 6400;     // per-kh [3 kw][64 ci][128 oc]
    int tx = threadIdx.x, ty = threadIdx.y, tz = threadIdx.z;  // (8,8,8)
    int tid = (tz*8 + ty)*8 + tx;                               // 0..511
    const float* inp = g_buf4 + (size_t)t*16384 + b*4096;
    for (int i = tid; i < 6400; i += 512){
        int c = i & 63; int xy = i >> 6; int x = xy % 10; int y = xy / 10;
        int h = y-1, w = x-1;
        float v = 0.f;
        if ((unsigned)h < 8u && (unsigned)w < 8u) v = inp[(h*8+w)*64 + c];
        tile[i] = v;
    }
    int ox = tx, oy = ty, og = tz;      // og in 0..7, 16 oc each
    u64 acc[8], tot[8];
    #pragma unroll
    for (int i=0;i<8;i++){ acc[i]=0ULL; tot[i]=0ULL; }
    for (int kh=0; kh<3; kh++){
        __syncthreads();
        const float4* wsrc = ((const float4*)g_w3t) + kh*3*64*32;
        for (int i = tid; i < 6144; i += 512) ((float4*)wsm)[i] = wsrc[i];
        __syncthreads();
        const u64* wsm64 = (const u64*)wsm;
        if (kh == 0){
            #pragma unroll
            for (int kw=0;kw<3;kw++){
                const float* trow = tile + ((oy+0)*10 + ox+kw)*64;
                accP<8>(acc, trow, wsm64 + kw*4096 + og*8, 64, 0, 64);
            }
        } else if (kh == 1){
            {   const float* trow = tile + ((oy+1)*10 + ox+0)*64;
                accP<8>(acc, trow, wsm64 + 0*4096 + og*8, 64, 0, 56);
                #pragma unroll
                for (int i=0;i<8;i++){ tot[i] = add2(tot[i], acc[i]); acc[i]=0ULL; }
                accP<8>(acc, trow, wsm64 + 0*4096 + og*8, 64, 56, 64);
            }
            #pragma unroll
            for (int kw=1;kw<3;kw++){
                const float* trow = tile + ((oy+1)*10 + ox+kw)*64;
                accP<8>(acc, trow, wsm64 + kw*4096 + og*8, 64, 0, 64);
            }
        } else {
            {   const float* trow = tile + ((oy+2)*10 + ox+0)*64;
                accP<8>(acc, trow, wsm64 + 0*4096 + og*8, 64, 0, 64);
            }
            {   const float* trow = tile + ((oy+2)*10 + ox+1)*64;
                accP<8>(acc, trow, wsm64 + 1*4096 + og*8, 64, 0, 48);
                #pragma unroll
                for (int i=0;i<8;i++){ tot[i] = add2(tot[i], acc[i]); acc[i]=0ULL; }
                accP<8>(acc, trow, wsm64 + 1*4096 + og*8, 64, 48, 64);
            }
            {   const float* trow = tile + ((oy+2)*10 + ox+2)*64;
                accP<8>(acc, trow, wsm64 + 2*4096 + og*8, 64, 0, 64);
            }
        }
    }
    #pragma unroll
    for (int i=0;i<8;i++) tot[i] = add2(tot[i], acc[i]);
    float2* op = (float2*)(g_buf5 + (size_t)t*32768 + b*8192 + (oy*8+ox)*128 + og*16);
    #pragma unroll
    for (int q=0;q<8;q++) op[q] = *reinterpret_cast<float2*>(&tot[q]);
}

// ---------------- dense1: 2048 -> 256. K = 8x248 + 64 panels -------------------
__global__ void dense1_kernel(){
    __shared__ float xs[8][KC];
    int row0 = blockIdx.x*8;
    int o = threadIdx.x;                  // 256 outputs
    float acc[8], tot[8];
    #pragma unroll
    for (int r=0;r<8;r++){ acc[r]=0.f; tot[r]=0.f; }
    int k0 = 0;
    for (int p=0; p<9; p++){
        int L = (p<8) ? KC : (2048 - 8*KC);
        __syncthreads();
        for (int i=threadIdx.x; i<8*L; i+=256){
            int r = i / L, kk = i - r*L;
            int k = k0 + kk;              // reference k = c*16 + h*4 + w
            int c = k >> 4, hw = k & 15;  // buf6 is [hw][c] channel-minor
            xs[r][kk] = g_buf6[(size_t)(row0+r)*2048 + hw*128 + c];
        }
        __syncthreads();
        for (int kk=0; kk<L; kk++){
            float wv = g_w4at[(size_t)(k0+kk)*256 + o];
            #pragma unroll
            for (int r=0;r<8;r++) acc[r] = __fmaf_rn(xs[r][kk], wv, acc[r]);
        }
        #pragma unroll
        for (int r=0;r<8;r++){ tot[r] = __fadd_rn(tot[r], acc[r]); acc[r]=0.f; }
        k0 += L;
    }
    for (int r=0;r<8;r++) g_buf7[(size_t)(row0+r)*256 + o] = tot[r];
}

// ---------------- dense2: 256 -> 11. K = 248 + 8 panels ------------------------
__global__ void dense2_kernel(const float* __restrict__ w4b){
    int tb = blockIdx.x;                  // t*4+b
    __shared__ float xs[256];
    int tid = threadIdx.x;                // 64
    for (int i=tid;i<256;i+=64) xs[i] = g_buf7[(size_t)tb*256 + i];
    __syncthreads();
    if (tid < 11){
        float acc = 0.f;
        for (int k=0;k<KC;k++)  acc = __fmaf_rn(xs[k], w4b[tid*256+k], acc);
        float tot = acc; acc = 0.f;
        for (int k=KC;k<256;k++) acc = __fmaf_rn(xs[k], w4b[tid*256+k], acc);
        tot = __fadd_rn(tot, acc);
        int t = tb >> 2, b = tb & 3;
        g_buf8[t*44 + b*11 + tid] = tot;
    }
}

// ---------------- final scan, output layout [b][o][t] --------------------------
__global__ void scan_out_kernel(float* __restrict__ out){
    int n = threadIdx.x;
    if (n >= 44) return;
    int b = n/11, o = n - b*11;
    float s1=0.f, s2=0.f, r1=0.f, r2=0.f;
    #pragma unroll 4
    for (int t=0;t<TT;t++){
        float x = g_buf8[t*44 + n];
        s2 = __fmul_rn(DCAY, __fadd_rn(s2, s1));
        s1 = __fadd_rn(__fmul_rn(DCAY, s1), x);
        r2 = __fmul_rn(DCAY, __fadd_rn(r2, r1));
        r1 = __fmul_rn(DCAY, r1);
        float u = __fmul_rn(PSPS, s2);
        float v = __fsub_rn(__fsub_rn(u, __fmul_rn(REFS, r2)), THR);
        float spk = (v >= 0.f) ? 1.f : 0.f;
        r1 = __fadd_rn(r1, spk);
        out[(size_t)(b*11+o)*TT + t] = spk;
    }
}

extern "C" void kernel_launch(void* const* d_in, const int* in_sizes, int n_in,
                              void* d_out, int out_size){
    const float* s_in = (const float*)d_in[0];
    const float* w1   = (const float*)d_in[1];
    const float* w2   = (const float*)d_in[2];
    const float* w3   = (const float*)d_in[3];
    const float* w4a  = (const float*)d_in[4];
    const float* w4b  = (const float*)d_in[5];
    float* out = (float*)d_out;

    float *b0,*b1,*b2,*b3,*b4,*b5,*b6,*b7;
    cudaGetSymbolAddress((void**)&b0, g_buf0);
    cudaGetSymbolAddress((void**)&b1, g_buf1);
    cudaGetSymbolAddress((void**)&b2, g_buf2);
    cudaGetSymbolAddress((void**)&b3, g_buf3);
    cudaGetSymbolAddress((void**)&b4, g_buf4);
    cudaGetSymbolAddress((void**)&b5, g_buf5);
    cudaGetSymbolAddress((void**)&b6, g_buf6);
    cudaGetSymbolAddress((void**)&b7, g_buf7);

    static bool attr_done = false;
    if (!attr_done){
        cudaFuncSetAttribute(conv2_kernel, cudaFuncAttributeMaxDynamicSharedMemorySize, 180736);
        cudaFuncSetAttribute(conv3_kernel, cudaFuncAttributeMaxDynamicSharedMemorySize, 123904);
        attr_done = true;
    }

    prep_all_k<<<2048,256>>>(w1, w2, w3, w4a);

    pool0_kernel<<<dim3(10,1024), dim3(32,8)>>>(s_in);
    scan_kernel<<<32,256>>>(b0, 8192);

    conv1_kernel<<<1200, dim3(32,16)>>>();
    scan2_pool_kernel<32,32><<<128,256>>>(b1, b2);

    conv2_kernel<<<1200, dim3(16,16,2), 180736>>>();
    scan2_pool_kernel<64,16><<<64,256>>>(b3, b4);

    conv3_kernel<<<1200, dim3(8,8,8), 123904>>>();
    scan2_pool_kernel<128,8><<<32,256>>>(b5, b6);

    dense1_kernel<<<150,256>>>();
    scan_kernel<<<4,256>>>(b7, 1024);

    dense2_kernel<<<1200,64>>>(w4b);
    scan_out_kernel<<<1,64>>>(out);
}

// round 13
// speedup vs baseline: 1.0401x; 1.0401x over previous
#include <cuda_runtime.h>

#define TT 300
#define NB 4

// f32-rounded versions of the reference's double constants
#define DCAY 0.8187307530779818f   // exp(-1/5)
#define PSPS 0.5436563656918091f   // e/5
#define REFS 1.3591409142295226f   // 2*1.25*e/5
#define THR  1.25f
#define PW   1.375f                // 1.1*theta (exact in f32)

#define KC 248                     // Eigen depth-panel size (ARM defaults)

typedef unsigned long long u64;

// ---- packed f32x2 helpers: per-lane rounding identical to scalar FFMA/FADD ----
__device__ __forceinline__ u64 pk2(float v){
    u64 r; asm("mov.b64 %0, {%1, %1};" : "=l"(r) : "f"(v)); return r;
}
__device__ __forceinline__ u64 fma2(u64 v, u64 w, u64 a){
    u64 r; asm("fma.rn.f32x2 %0, %1, %2, %3;" : "=l"(r) : "l"(v), "l"(w), "l"(a)); return r;
}
__device__ __forceinline__ u64 add2(u64 a, u64 b){
    u64 r; asm("add.rn.f32x2 %0, %1, %2;" : "=l"(r) : "l"(a), "l"(b)); return r;
}

// ---- scratch, time-major, CHANNEL-MINOR spatial layouts ----
__device__ float g_buf0[TT*8192];     // [t][4][32][32][2]
__device__ float g_buf1[TT*131072];   // [t][4][32][32][32]  conv1 raw
__device__ float g_buf2[TT*32768];    // [t][4][16][16][32]
__device__ float g_buf3[TT*65536];    // [t][4][16][16][64]  conv2 raw
__device__ float g_buf4[TT*16384];    // [t][4][8][8][64]
__device__ float g_buf5[TT*32768];    // [t][4][8][8][128]   conv3 raw
__device__ float g_buf6[TT*8192];     // [t][4][4][4][128]
__device__ float g_buf7[TT*1024];     // [t][4][256]
__device__ float g_buf8[TT*44];       // [t][4][11]

// weights transposed to [kh][kw][ci][oc] (HWIO): k-ascending == (kh,kw,ci), ci fastest
__device__ __align__(16) float g_w1t[50*32];
__device__ __align__(16) float g_w2t[288*64];
__device__ __align__(16) float g_w3t[576*128];
__device__ __align__(16) float g_w4at[2048*256];   // [k][o]

// ---------------- merged weight transpose (single launch) ----------------
__global__ void prep_all_k(const float* __restrict__ w1, const float* __restrict__ w2,
                           const float* __restrict__ w3, const float* __restrict__ w4a){
    int i = blockIdx.x*256 + threadIdx.x;
    if (i < 32*50){
        int o = i/50, rem = i%50;
        int c = rem/25, r = rem%25, kh = r/5, kw = r%5;
        g_w1t[((kh*5+kw)*2 + c)*32 + o] = w1[i];
    }
    if (i < 64*288){
        int o = i/288, rem = i%288;
        int ci = rem/9, r = rem%9, kh = r/3, kw = r%3;
        g_w2t[((kh*3+kw)*32 + ci)*64 + o] = w2[i];
    }
    if (i < 128*576){
        int o = i/576, rem = i%576;
        int ci = rem/9, r = rem%9, kh = r/3, kw = r%3;
        g_w3t[((kh*3+kw)*64 + ci)*128 + o] = w3[i];
    }
    if (i < 256*2048){
        int o = i/2048, k = i%2048;
        g_w4at[k*256+o] = w4a[i];
    }
}

// ---------------- stage 0: 4x4 sum-pool (binary inputs -> exact) ----------------
__global__ void pool0_kernel(const float* __restrict__ s){
    int t = blockIdx.x*32 + threadIdx.x;
    int n = blockIdx.y*blockDim.y + threadIdx.y;
    if (t >= TT) return;
    int c = n & 1, ow = (n>>1)&31, oh = (n>>6)&31, b = n>>11;
    const float* base = s + (size_t)(((b*2+c)*128 + oh*4)*128 + ow*4)*TT + t;
    float acc = 0.f;
    #pragma unroll
    for (int i=0;i<4;i++)
        #pragma unroll
        for (int j=0;j<4;j++)
            acc += base[(i*128+j)*TT];
    g_buf0[(size_t)t*8192 + n] = acc * PW;
}

// ---------------- fused PSP + refractory + threshold scan (strict rn) ----------
__global__ void scan_kernel(float* __restrict__ buf, int N){
    int n = blockIdx.x*blockDim.x + threadIdx.x;
    if (n >= N) return;
    float s1=0.f, s2=0.f, r1=0.f, r2=0.f;
    size_t idx = n;
    float a = buf[idx];
    #pragma unroll 2
    for (int t=0; t<TT; t++, idx += N){
        float nx = 0.f;
        if (t+1 < TT) nx = buf[idx + N];        // prefetch next step
        float x = a;
        s2 = __fmul_rn(DCAY, __fadd_rn(s2, s1));
        s1 = __fadd_rn(__fmul_rn(DCAY, s1), x);
        r2 = __fmul_rn(DCAY, __fadd_rn(r2, r1));
        r1 = __fmul_rn(DCAY, r1);
        float u = __fmul_rn(PSPS, s2);
        float v = __fsub_rn(__fsub_rn(u, __fmul_rn(REFS, r2)), THR);
        float spk = (v >= 0.f) ? 1.f : 0.f;
        r1 = __fadd_rn(r1, spk);
        buf[idx] = spk;
        a = nx;
    }
}

// ---------------- fused: scan(conv raw) -> 2x2 pool -> scan(pooled) ------------
// Bit-identical to scan + pool + scan: same strict-rn sequence per t-step.
template<int C, int Hin>
__global__ void scan2_pool_kernel(const float* __restrict__ in, float* __restrict__ out){
    const int Ho = Hin/2;
    const int Npool = 4*C*Ho*Ho;
    const int Tin = 4*C*Hin*Hin;
    int n = blockIdx.x*256 + threadIdx.x;
    int c = n & (C-1);
    int r = n / C;
    int ow = r % Ho; r /= Ho;
    int oh = r % Ho;
    int b = r / Ho;
    size_t base = ((size_t)(b*Hin + 2*oh)*Hin + 2*ow)*C + c;
    float S1[4]={0,0,0,0}, S2[4]={0,0,0,0}, R1[4]={0,0,0,0}, R2[4]={0,0,0,0};
    float ps1=0.f, ps2=0.f, pr1=0.f, pr2=0.f;
    const int off1 = C, off2 = Hin*C, off3 = Hin*C + C;
    const float* p = in + base;
    float a0=p[0], a1=p[off1], a2=p[off2], a3=p[off3];
    #pragma unroll 2
    for (int t=0; t<TT; t++){
        float b0=0.f,b1=0.f,b2=0.f,b3=0.f;
        if (t+1 < TT){                          // prefetch next step
            const float* pn = in + (size_t)(t+1)*Tin + base;
            b0=pn[0]; b1=pn[off1]; b2=pn[off2]; b3=pn[off3];
        }
        float xs[4] = {a0, a1, a2, a3};
        float sum = 0.f;
        #pragma unroll
        for (int j=0;j<4;j++){
            S2[j] = __fmul_rn(DCAY, __fadd_rn(S2[j], S1[j]));
            S1[j] = __fadd_rn(__fmul_rn(DCAY, S1[j]), xs[j]);
            R2[j] = __fmul_rn(DCAY, __fadd_rn(R2[j], R1[j]));
            R1[j] = __fmul_rn(DCAY, R1[j]);
            float u = __fmul_rn(PSPS, S2[j]);
            float v = __fsub_rn(__fsub_rn(u, __fmul_rn(REFS, R2[j])), THR);
            float spk = (v >= 0.f) ? 1.f : 0.f;
            R1[j] = __fadd_rn(R1[j], spk);
            sum += spk;                         // exact: small integers
        }
        float x = sum * PW;                     // exact
        ps2 = __fmul_rn(DCAY, __fadd_rn(ps2, ps1));
        ps1 = __fadd_rn(__fmul_rn(DCAY, ps1), x);
        pr2 = __fmul_rn(DCAY, __fadd_rn(pr2, pr1));
        pr1 = __fmul_rn(DCAY, pr1);
        float u = __fmul_rn(PSPS, ps2);
        float v = __fsub_rn(__fsub_rn(u, __fmul_rn(REFS, pr2)), THR);
        float spk = (v >= 0.f) ? 1.f : 0.f;
        pr1 = __fadd_rn(pr1, spk);
        out[(size_t)t*Npool + n] = spk;
        a0=b0; a1=b1; a2=b2; a3=b3;
    }
}

// ---------------- conv1: 2->32, 5x5 pad2, 32x32 --------------------------------
// block (32,8,2): tx=ox, ty=row base, tz=og (16 oc). 2 pixels/thread (rows oy, oy+8)
// reuse each weight load across both pixels; v loaded as float2 (both ci).
__global__ void __launch_bounds__(512,1) conv1_kernel(){
    int tb = blockIdx.x; int b = tb & 3; int t = tb >> 2;
    __shared__ float tile[36*36*2];
    __shared__ __align__(16) float ws[50*32];
    int tx = threadIdx.x, ty = threadIdx.y, tz = threadIdx.z;
    int tid = (tz*8 + ty)*32 + tx;          // 0..511
    const float* inp = g_buf0 + (size_t)t*8192 + b*2048;
    for (int i = tid; i < 36*36*2; i += 512){
        int c = i & 1; int xy = i >> 1; int x = xy % 36; int y = xy / 36;
        int h = y-2, w = x-2;
        float v = 0.f;
        if ((unsigned)h < 32u && (unsigned)w < 32u) v = inp[(h*32+w)*2 + c];
        tile[i] = v;
    }
    for (int i = tid; i < 400; i += 512) ((float4*)ws)[i] = ((const float4*)g_w1t)[i];
    __syncthreads();
    int ox = tx, og = tz;
    const u64* ws64 = (const u64*)ws;
    for (int s = 0; s < 2; s++){
        int oyA = ty + 16*s;                // pixel rows oyA, oyA+8
        u64 aA[8], aB[8];
        #pragma unroll
        for (int i=0;i<8;i++){ aA[i]=0ULL; aB[i]=0ULL; }
        for (int kh=0;kh<5;kh++)
            #pragma unroll
            for (int kw=0;kw<5;kw++){
                float2 vA2 = *(const float2*)(tile + ((oyA+kh)*36 + ox+kw)*2);
                float2 vB2 = *(const float2*)(tile + ((oyA+8+kh)*36 + ox+kw)*2);
                u64 vA0=pk2(vA2.x), vA1=pk2(vA2.y), vB0=pk2(vB2.x), vB1=pk2(vB2.y);
                const ulonglong2* w0 = (const ulonglong2*)(ws64 + ((kh*5+kw)*2+0)*16 + og*8);
                const ulonglong2* w1 = (const ulonglong2*)(ws64 + ((kh*5+kw)*2+1)*16 + og*8);
                #pragma unroll
                for (int q=0;q<4;q++){
                    ulonglong2 wc0 = w0[q];
                    ulonglong2 wc1 = w1[q];
                    aA[2*q]   = fma2(vA0, wc0.x, aA[2*q]);
                    aA[2*q+1] = fma2(vA0, wc0.y, aA[2*q+1]);
                    aB[2*q]   = fma2(vB0, wc0.x, aB[2*q]);
                    aB[2*q+1] = fma2(vB0, wc0.y, aB[2*q+1]);
                    aA[2*q]   = fma2(vA1, wc1.x, aA[2*q]);
                    aA[2*q+1] = fma2(vA1, wc1.y, aA[2*q+1]);
                    aB[2*q]   = fma2(vB1, wc1.x, aB[2*q]);
                    aB[2*q+1] = fma2(vB1, wc1.y, aB[2*q+1]);
                }
            }
        float2* opA = (float2*)(g_buf1 + (size_t)t*131072 + b*32768 + (oyA*32+ox)*32 + og*16);
        float2* opB = (float2*)(g_buf1 + (size_t)t*131072 + b*32768 + ((oyA+8)*32+ox)*32 + og*16);
        #pragma unroll
        for (int q=0;q<8;q++){ opA[q] = *reinterpret_cast<float2*>(&aA[q]);
                               opB[q] = *reinterpret_cast<float2*>(&aB[q]); }
    }
}

// ---------------- conv2: 32->64, 3x3 pad1, 16x16. K=288 = 248 + 40 ------------
// block (16,8,4): tx=ox, ty=row base (rows ty, ty+8), tz=og (16 oc = 8 u64/px).
// ci processed in pairs (float2 v); panel boundary ci24 is pair-aligned.
extern __shared__ float s_dyn[];
__device__ __forceinline__ void c2_acc(u64* aA, u64* aB, const float* trowA, const float* trowB,
                                       const u64* wci, int cp0, int cp1){
    for (int cp=cp0; cp<cp1; cp++){
        float2 vA2 = *(const float2*)(trowA + 2*cp);
        float2 vB2 = *(const float2*)(trowB + 2*cp);
        u64 vA0=pk2(vA2.x), vA1=pk2(vA2.y), vB0=pk2(vB2.x), vB1=pk2(vB2.y);
        const ulonglong2* w0 = (const ulonglong2*)(wci + (2*cp)*32);
        const ulonglong2* w1 = (const ulonglong2*)(wci + (2*cp+1)*32);
        #pragma unroll
        for (int q=0;q<4;q++){
            ulonglong2 wc0 = w0[q];
            ulonglong2 wc1 = w1[q];
            aA[2*q]   = fma2(vA0, wc0.x, aA[2*q]);
            aA[2*q+1] = fma2(vA0, wc0.y, aA[2*q+1]);
            aB[2*q]   = fma2(vB0, wc0.x, aB[2*q]);
            aB[2*q+1] = fma2(vB0, wc0.y, aB[2*q+1]);
            aA[2*q]   = fma2(vA1, wc1.x, aA[2*q]);
            aA[2*q+1] = fma2(vA1, wc1.y, aA[2*q+1]);
            aB[2*q]   = fma2(vB1, wc1.x, aB[2*q]);
            aB[2*q+1] = fma2(vB1, wc1.y, aB[2*q+1]);
        }
    }
}
__global__ void __launch_bounds__(512,1) conv2_kernel(){
    int tb = blockIdx.x; int b = tb & 3; int t = tb >> 2;
    float* tile = s_dyn;                    // [18][18][32]  10368 f
    float* wsm  = s_dyn + 10368;            // [9 tap][32 ci][64 oc] 18432 f
    u64*  stash = (u64*)(s_dyn + 28800);    // 512 thr x 16 u64 = 64 KB
    int tx = threadIdx.x, ty = threadIdx.y, tz = threadIdx.z;  // (16,8,4)
    int tid = (tz*8 + ty)*16 + tx;                              // 0..511
    const float* inp = g_buf2 + (size_t)t*32768 + b*8192;
    for (int i = tid; i < 10368; i += 512){
        int c = i & 31; int xy = i >> 5; int x = xy % 18; int y = xy / 18;
        int h = y-1, w = x-1;
        float v = 0.f;
        if ((unsigned)h < 16u && (unsigned)w < 16u) v = inp[(h*16+w)*32 + c];
        tile[i] = v;
    }
    for (int i = tid; i < 4608; i += 512) ((float4*)wsm)[i] = ((const float4*)g_w2t)[i];
    __syncthreads();
    int ox = tx, og = tz;
    const u64* wsm64 = (const u64*)wsm;
    u64 aA[8], aB[8];
    #pragma unroll
    for (int i=0;i<8;i++){ aA[i]=0ULL; aB[i]=0ULL; }
    // panel B first: tap7 ci>=24 (pairs 12..15), tap8 full
    {
        const float* trowA7 = tile + ((ty+2)*18 + ox+1)*32;
        const float* trowB7 = trowA7 + 8*18*32;
        c2_acc(aA, aB, trowA7, trowB7, wsm64 + 7*1024 + og*8, 12, 16);
        const float* trowA8 = tile + ((ty+2)*18 + ox+2)*32;
        const float* trowB8 = trowA8 + 8*18*32;
        c2_acc(aA, aB, trowA8, trowB8, wsm64 + 8*1024 + og*8, 0, 16);
    }
    u64* st = stash + tid*16;
    #pragma unroll
    for (int i=0;i<8;i++){ st[i] = aA[i]; st[8+i] = aB[i]; aA[i]=0ULL; aB[i]=0ULL; }
    // panel A: taps 0..6 full, tap7 pairs 0..11 (ci<24)
    for (int tap=0; tap<7; tap++){
        const float* trowA = tile + ((ty + tap/3)*18 + ox + tap%3)*32;
        const float* trowB = trowA + 8*18*32;
        c2_acc(aA, aB, trowA, trowB, wsm64 + tap*1024 + og*8, 0, 16);
    }
    {
        const float* trowA7 = tile + ((ty+2)*18 + ox+1)*32;
        const float* trowB7 = trowA7 + 8*18*32;
        c2_acc(aA, aB, trowA7, trowB7, wsm64 + 7*1024 + og*8, 0, 12);
    }
    // combine panels (fadd bitwise-commutative -> same values as A+B order)
    #pragma unroll
    for (int i=0;i<8;i++){ aA[i] = add2(aA[i], st[i]); aB[i] = add2(aB[i], st[8+i]); }
    float2* opA = (float2*)(g_buf3 + (size_t)t*65536 + b*16384 + (ty*16+ox)*64 + og*16);
    float2* opB = (float2*)(g_buf3 + (size_t)t*65536 + b*16384 + ((ty+8)*16+ox)*64 + og*16);
    #pragma unroll
    for (int q=0;q<8;q++){ opA[q] = *reinterpret_cast<float2*>(&aA[q]);
                           opB[q] = *reinterpret_cast<float2*>(&aB[q]); }
}

// ---------------- conv3: 64->128, 3x3 pad1, 8x8. K=576 = 248+248+80 -----------
// block (8,4,16): tx=ox, ty=row base (rows ty, ty+4), tz=og (8 oc = 4 u64/px).
// Boundaries: k=248 (tap3 ci56, pair 28), k=496 (tap7 ci48, pair 24).
__device__ __forceinline__ void c3_acc(u64* aA, u64* aB, const float* trowA, const float* trowB,
                                       const u64* wci, int cp0, int cp1){
    for (int cp=cp0; cp<cp1; cp++){
        float2 vA2 = *(const float2*)(trowA + 2*cp);
        float2 vB2 = *(const float2*)(trowB + 2*cp);
        u64 vA0=pk2(vA2.x), vA1=pk2(vA2.y), vB0=pk2(vB2.x), vB1=pk2(vB2.y);
        const ulonglong2* w0 = (const ulonglong2*)(wci + (2*cp)*64);
        const ulonglong2* w1 = (const ulonglong2*)(wci + (2*cp+1)*64);
        #pragma unroll
        for (int q=0;q<2;q++){
            ulonglong2 wc0 = w0[q];
            ulonglong2 wc1 = w1[q];
            aA[2*q]   = fma2(vA0, wc0.x, aA[2*q]);
            aA[2*q+1] = fma2(vA0, wc0.y, aA[2*q+1]);
            aB[2*q]   = fma2(vB0, wc0.x, aB[2*q]);
            aB[2*q+1] = fma2(vB0, wc0.y, aB[2*q+1]);
            aA[2*q]   = fma2(vA1, wc1.x, aA[2*q]);
            aA[2*q+1] = fma2(vA1, wc1.y, aA[2*q+1]);
            aB[2*q]   = fma2(vB1, wc1.x, aB[2*q]);
            aB[2*q+1] = fma2(vB1, wc1.y, aB[2*q+1]);
        }
    }
}
__global__ void __launch_bounds__(512,1) conv3_kernel(){
    int tb = blockIdx.x; int b = tb & 3; int t = tb >> 2;
    float* tile = s_dyn;            // [10][10][64]  6400 f
    float* wsm  = s_dyn + 6400;     // per-kh [3 kw][64 ci][128 oc] 24576 f
    int tx = threadIdx.x, ty = threadIdx.y, tz = threadIdx.z;  // (8,4,16)
    int tid = (tz*4 + ty)*8 + tx;                               // 0..511
    const float* inp = g_buf4 + (size_t)t*16384 + b*4096;
    for (int i = tid; i < 6400; i += 512){
        int c = i & 63; int xy = i >> 6; int x = xy % 10; int y = xy / 10;
        int h = y-1, w = x-1;
        float v = 0.f;
        if ((unsigned)h < 8u && (unsigned)w < 8u) v = inp[(h*8+w)*64 + c];
        tile[i] = v;
    }
    int ox = tx, og = tz;
    u64 aA[4], aB[4], tA[4], tB[4];
    #pragma unroll
    for (int i=0;i<4;i++){ aA[i]=0ULL; aB[i]=0ULL; tA[i]=0ULL; tB[i]=0ULL; }
    for (int kh=0; kh<3; kh++){
        __syncthreads();
        const float4* wsrc = ((const float4*)g_w3t) + kh*3*64*32;
        for (int i = tid; i < 6144; i += 512) ((float4*)wsm)[i] = wsrc[i];
        __syncthreads();
        const u64* wsm64 = (const u64*)wsm;
        const float* rA = tile + (ty+kh)*10*64;
        const float* rB = tile + (ty+4+kh)*10*64;
        if (kh == 0){
            #pragma unroll
            for (int kw=0;kw<3;kw++)
                c3_acc(aA, aB, rA + (ox+kw)*64, rB + (ox+kw)*64, wsm64 + kw*4096 + og*4, 0, 32);
        } else if (kh == 1){
            c3_acc(aA, aB, rA + ox*64, rB + ox*64, wsm64 + 0*4096 + og*4, 0, 28);
            #pragma unroll
            for (int i=0;i<4;i++){ tA[i]=add2(tA[i],aA[i]); tB[i]=add2(tB[i],aB[i]); aA[i]=0ULL; aB[i]=0ULL; }
            c3_acc(aA, aB, rA + ox*64, rB + ox*64, wsm64 + 0*4096 + og*4, 28, 32);
            #pragma unroll
            for (int kw=1;kw<3;kw++)
                c3_acc(aA, aB, rA + (ox+kw)*64, rB + (ox+kw)*64, wsm64 + kw*4096 + og*4, 0, 32);
        } else {
            c3_acc(aA, aB, rA + ox*64, rB + ox*64, wsm64 + 0*4096 + og*4, 0, 32);
            c3_acc(aA, aB, rA + (ox+1)*64, rB + (ox+1)*64, wsm64 + 1*4096 + og*4, 0, 24);
            #pragma unroll
            for (int i=0;i<4;i++){ tA[i]=add2(tA[i],aA[i]); tB[i]=add2(tB[i],aB[i]); aA[i]=0ULL; aB[i]=0ULL; }
            c3_acc(aA, aB, rA + (ox+1)*64, rB + (ox+1)*64, wsm64 + 1*4096 + og*4, 24, 32);
            c3_acc(aA, aB, rA + (ox+2)*64, rB + (ox+2)*64, wsm64 + 2*4096 + og*4, 0, 32);
        }
    }
    #pragma unroll
    for (int i=0;i<4;i++){ tA[i]=add2(tA[i],aA[i]); tB[i]=add2(tB[i],aB[i]); }
    float2* opA = (float2*)(g_buf5 + (size_t)t*32768 + b*8192 + (ty*8+ox)*128 + og*8);
    float2* opB = (float2*)(g_buf5 + (size_t)t*32768 + b*8192 + ((ty+4)*8+ox)*128 + og*8);
    #pragma unroll
    for (int q=0;q<4;q++){ opA[q] = *reinterpret_cast<float2*>(&tA[q]);
                           opB[q] = *reinterpret_cast<float2*>(&tB[q]); }
}

// ---------------- dense1: 2048 -> 256. K = 8x248 + 64 panels -------------------
__global__ void dense1_kernel(){
    __shared__ float xs[8][KC];
    int row0 = blockIdx.x*8;
    int o = threadIdx.x;
    float acc[8], tot[8];
    #pragma unroll
    for (int r=0;r<8;r++){ acc[r]=0.f; tot[r]=0.f; }
    int k0 = 0;
    for (int p=0; p<9; p++){
        int L = (p<8) ? KC : (2048 - 8*KC);
        __syncthreads();
        for (int i=threadIdx.x; i<8*L; i+=256){
            int r = i / L, kk = i - r*L;
            int k = k0 + kk;
            int c = k >> 4, hw = k & 15;
            xs[r][kk] = g_buf6[(size_t)(row0+r)*2048 + hw*128 + c];
        }
        __syncthreads();
        for (int kk=0; kk<L; kk++){
            float wv = g_w4at[(size_t)(k0+kk)*256 + o];
            #pragma unroll
            for (int r=0;r<8;r++) acc[r] = __fmaf_rn(xs[r][kk], wv, acc[r]);
        }
        #pragma unroll
        for (int r=0;r<8;r++){ tot[r] = __fadd_rn(tot[r], acc[r]); acc[r]=0.f; }
        k0 += L;
    }
    for (int r=0;r<8;r++) g_buf7[(size_t)(row0+r)*256 + o] = tot[r];
}

// ---------------- dense2: 256 -> 11. K = 248 + 8 panels ------------------------
__global__ void dense2_kernel(const float* __restrict__ w4b){
    int tb = blockIdx.x;
    __shared__ float xs[256];
    int tid = threadIdx.x;
    for (int i=tid;i<256;i+=64) xs[i] = g_buf7[(size_t)tb*256 + i];
    __syncthreads();
    if (tid < 11){
        float acc = 0.f;
        for (int k=0;k<KC;k++)  acc = __fmaf_rn(xs[k], w4b[tid*256+k], acc);
        float tot = acc; acc = 0.f;
        for (int k=KC;k<256;k++) acc = __fmaf_rn(xs[k], w4b[tid*256+k], acc);
        tot = __fadd_rn(tot, acc);
        int t = tb >> 2, b = tb & 3;
        g_buf8[t*44 + b*11 + tid] = tot;
    }
}

// ---------------- final scan, output layout [b][o][t] --------------------------
__global__ void scan_out_kernel(float* __restrict__ out){
    int n = threadIdx.x;
    if (n >= 44) return;
    int b = n/11, o = n - b*11;
    float s1=0.f, s2=0.f, r1=0.f, r2=0.f;
    #pragma unroll 4
    for (int t=0;t<TT;t++){
        float x = g_buf8[t*44 + n];
        s2 = __fmul_rn(DCAY, __fadd_rn(s2, s1));
        s1 = __fadd_rn(__fmul_rn(DCAY, s1), x);
        r2 = __fmul_rn(DCAY, __fadd_rn(r2, r1));
        r1 = __fmul_rn(DCAY, r1);
        float u = __fmul_rn(PSPS, s2);
        float v = __fsub_rn(__fsub_rn(u, __fmul_rn(REFS, r2)), THR);
        float spk = (v >= 0.f) ? 1.f : 0.f;
        r1 = __fadd_rn(r1, spk);
        out[(size_t)(b*11+o)*TT + t] = spk;
    }
}

extern "C" void kernel_launch(void* const* d_in, const int* in_sizes, int n_in,
                              void* d_out, int out_size){
    const float* s_in = (const float*)d_in[0];
    const float* w1   = (const float*)d_in[1];
    const float* w2   = (const float*)d_in[2];
    const float* w3   = (const float*)d_in[3];
    const float* w4a  = (const float*)d_in[4];
    const float* w4b  = (const float*)d_in[5];
    float* out = (float*)d_out;

    float *b0,*b1,*b3,*b5,*b7;
    cudaGetSymbolAddress((void**)&b0, g_buf0);
    cudaGetSymbolAddress((void**)&b1, g_buf1);
    cudaGetSymbolAddress((void**)&b3, g_buf3);
    cudaGetSymbolAddress((void**)&b5, g_buf5);
    cudaGetSymbolAddress((void**)&b7, g_buf7);
    float *b2,*b4,*b6;
    cudaGetSymbolAddress((void**)&b2, g_buf2);
    cudaGetSymbolAddress((void**)&b4, g_buf4);
    cudaGetSymbolAddress((void**)&b6, g_buf6);

    static bool attr_done = false;
    if (!attr_done){
        cudaFuncSetAttribute(conv2_kernel, cudaFuncAttributeMaxDynamicSharedMemorySize, 180736);
        cudaFuncSetAttribute(conv3_kernel, cudaFuncAttributeMaxDynamicSharedMemorySize, 123904);
        attr_done = true;
    }

    prep_all_k<<<2048,256>>>(w1, w2, w3, w4a);

    pool0_kernel<<<dim3(10,1024), dim3(32,8)>>>(s_in);
    scan_kernel<<<32,256>>>(b0, 8192);

    conv1_kernel<<<1200, dim3(32,8,2)>>>();
    scan2_pool_kernel<32,32><<<128,256>>>(b1, b2);

    conv2_kernel<<<1200, dim3(16,8,4), 180736>>>();
    scan2_pool_kernel<64,16><<<64,256>>>(b3, b4);

    conv3_kernel<<<1200, dim3(8,4,16), 123904>>>();
    scan2_pool_kernel<128,8><<<32,256>>>(b5, b6);

    dense1_kernel<<<150,256>>>();
    scan_kernel<<<4,256>>>(b7, 1024);

    dense2_kernel<<<1200,64>>>(w4b);
    scan_out_kernel<<<1,64>>>(out);
}